// round 2
// baseline (speedup 1.0000x reference)
#include <cuda_runtime.h>
#include <math.h>
#include <stdint.h>

#define Gn   1024
#define NIN  64
#define Hh   128
#define Bsz  256
#define Pn   523776
#define KC   1024
#define KT   16
#define NCHUNK 512   // ceil(Pn / KC)

// ---------------- device scratch (no allocations allowed) ----------------
__device__ float        g_EmT[Gn * Bsz];   // exp(-c) transposed: [g][b]
__device__ float        g_EpT[Gn * Bsz];   // exp(+c) transposed: [g][b]
__device__ unsigned int g_pairs[Pn];       // (i<<16)|j
__device__ float        g_h  [Bsz * Hh];   // split-K accumulator
__device__ float        g_hn [Bsz * Hh];   // post-BN ReLU hidden

// ---------------- f32x2 packed FMA helpers ----------------
typedef unsigned long long ull;

__device__ __forceinline__ ull pk2(float v) {
    ull r;
    asm("mov.b64 %0, {%1, %2};" : "=l"(r) : "f"(v), "f"(v));
    return r;
}
__device__ __forceinline__ void fma2(ull& d, ull a, ull b) {
    asm("fma.rn.f32x2 %0, %1, %2, %0;" : "+l"(d) : "l"(a), "l"(b));
}
__device__ __forceinline__ void upk2(ull v, float& lo, float& hi) {
    asm("mov.b64 {%0, %1}, %2;" : "=f"(lo), "=f"(hi) : "l"(v));
}

// ---------------- kernel 0: build pair index table ----------------
__global__ void k_pairs() {
    int i = blockIdx.x;
    if (i >= Gn - 1) return;
    int off = i * (Gn - 1) - (i * (i - 1)) / 2;  // pairs before row i
    for (int j = i + 1 + threadIdx.x; j < Gn; j += blockDim.x)
        g_pairs[off + (j - i - 1)] = ((unsigned)i << 16) | (unsigned)j;
}

// ---------------- kernel 1: c = z@Wc.T + bc ; exp tables ; zero g_h ------
__global__ void k_cexp(const float* __restrict__ z,
                       const float* __restrict__ Wc,
                       const float* __restrict__ bc) {
    int b = blockIdx.x;
    int t = threadIdx.x;
    int w = t >> 5, l = t & 31;
    __shared__ float zv[NIN];
    if (t < NIN) zv[t] = z[b * NIN + t];
    if (t < Hh)  g_h[b * Hh + t] = 0.f;
    __syncthreads();
    float z0 = zv[2 * l], z1 = zv[2 * l + 1];
    for (int g = w; g < Gn; g += 8) {
        float2 wv = *(const float2*)(Wc + (size_t)g * NIN + 2 * l);
        float p = wv.x * z0 + wv.y * z1;
        #pragma unroll
        for (int o = 16; o > 0; o >>= 1)
            p += __shfl_xor_sync(0xffffffffu, p, o);
        if (l == 0) {
            float c = p + bc[g];
            g_EmT[g * Bsz + b] = expf(-c);
            g_EpT[g * Bsz + b] = expf(c);
        }
    }
}

// ---------------- kernel 2: fused sigma gen + write + split-K SGEMM ------
// grid: (NCHUNK, 2)  block: 256.  CTA tile: 128 batch rows x 128 hidden.
__global__ void __launch_bounds__(256, 2)
k_gemm(const float* __restrict__ W1, float* __restrict__ outSigma) {
    const int p0     = blockIdx.x * KC;
    int rem          = Pn - p0;
    const int nsteps = (rem < KC ? rem : KC) >> 4;  // chunk len is mult of 16
    const int btile  = blockIdx.y * 128;
    const int t      = threadIdx.x;

    __shared__ float sA[KT][132];  // sigma  [k][b]
    __shared__ float sB[KT][132];  // W1^T   [k][hh]

    ull acc2[4][8];
    #pragma unroll
    for (int i = 0; i < 4; i++)
        #pragma unroll
        for (int j = 0; j < 8; j++) acc2[i][j] = 0ull;

    const int ty = t >> 4, tx = t & 15;
    const int m0 = ty * 4, n0 = tx * 4;
    const int gb = t & 127;            // sigma-gen batch lane
    const int kh = (t >> 7) * 8;       // sigma-gen k half
    const int wf = t & 3;              // float4 slot (W1 load & sigma store)
    const int wh = t >> 2;             // row 0..63

    for (int s = 0; s < nsteps; s++) {
        const int pk = p0 + s * KT;
        __syncthreads();

        // --- generate sigma tile (coalesced over b) ---
        #pragma unroll
        for (int r = 0; r < 8; r++) {
            int k = kh + r;
            unsigned u = __ldg(&g_pairs[pk + k]);
            int i = (int)(u >> 16), j = (int)(u & 0xffffu);
            float em = g_EmT[i * Bsz + btile + gb];
            float ep = g_EpT[j * Bsz + btile + gb];
            sA[k][gb] = em * ep;
        }
        // --- load W1 tile, transpose into sB[k][hh] ---
        #pragma unroll
        for (int r = 0; r < 2; r++) {
            int hh = wh + 64 * r;
            float4 wv = *(const float4*)(W1 + (size_t)hh * Pn + pk + 4 * wf);
            sB[4 * wf + 0][hh] = wv.x;
            sB[4 * wf + 1][hh] = wv.y;
            sB[4 * wf + 2][hh] = wv.z;
            sB[4 * wf + 3][hh] = wv.w;
        }
        __syncthreads();

        // --- write sigma to output (float4, 64B contiguous per row) ---
        #pragma unroll
        for (int r = 0; r < 2; r++) {
            int b = wh + 64 * r;
            float4 v;
            v.x = sA[4 * wf + 0][b];
            v.y = sA[4 * wf + 1][b];
            v.z = sA[4 * wf + 2][b];
            v.w = sA[4 * wf + 3][b];
            *(float4*)(outSigma + (size_t)(btile + b) * Pn + pk + 4 * wf) = v;
        }

        // --- 8x8 microkernel with packed f32x2 FMA ---
        #pragma unroll
        for (int kk = 0; kk < KT; kk++) {
            ulonglong2 A0 = *(const ulonglong2*)&sA[kk][m0];
            ulonglong2 A1 = *(const ulonglong2*)&sA[kk][64 + m0];
            float4 b0 = *(const float4*)&sB[kk][n0];
            float4 b1 = *(const float4*)&sB[kk][64 + n0];
            ull Av[4] = {A0.x, A0.y, A1.x, A1.y};
            ull Bd[8] = {pk2(b0.x), pk2(b0.y), pk2(b0.z), pk2(b0.w),
                         pk2(b1.x), pk2(b1.y), pk2(b1.z), pk2(b1.w)};
            #pragma unroll
            for (int i = 0; i < 4; i++)
                #pragma unroll
                for (int j = 0; j < 8; j++)
                    fma2(acc2[i][j], Av[i], Bd[j]);
        }
    }

    // --- epilogue: fp32 atomic reduction into g_h ---
    const int mb[4] = {m0, m0 + 2, 64 + m0, 64 + m0 + 2};
    #pragma unroll
    for (int i = 0; i < 4; i++) {
        #pragma unroll
        for (int j = 0; j < 8; j++) {
            float lo, hi;
            upk2(acc2[i][j], lo, hi);
            int n = (j < 4) ? (n0 + j) : (64 + n0 + j - 4);
            atomicAdd(&g_h[(btile + mb[i]) * Hh + n], lo);
            atomicAdd(&g_h[(btile + mb[i] + 1) * Hh + n], hi);
        }
    }
}

// ---------------- kernel 3: BatchNorm (training stats) + ReLU ------------
__global__ void k_bn(const float* __restrict__ b1,
                     const float* __restrict__ gamma,
                     const float* __restrict__ beta) {
    int hh = threadIdx.x;  // 128 threads
    float bb = b1[hh];
    float s = 0.f, ss = 0.f;
    #pragma unroll 4
    for (int b = 0; b < Bsz; b++) {
        float v = g_h[b * Hh + hh] + bb;
        s += v; ss += v * v;
    }
    float mean = s * (1.f / Bsz);
    float var  = ss * (1.f / Bsz) - mean * mean;
    float inv  = rsqrtf(var + 1e-3f);
    float ga = gamma[hh], be = beta[hh];
    #pragma unroll 4
    for (int b = 0; b < Bsz; b++) {
        float v = g_h[b * Hh + hh] + bb;
        float y = ga * (v - mean) * inv + be;
        g_hn[b * Hh + hh] = fmaxf(y, 0.f);
    }
}

// ---------------- kernel 4: heads + softmax ------------------------------
__global__ void k_heads(const float* __restrict__ Wscale, const float* __restrict__ bscale,
                        const float* __restrict__ Wshape, const float* __restrict__ bshape,
                        const float* __restrict__ Wdrop,  const float* __restrict__ bdrop,
                        float* __restrict__ out) {
    int b = blockIdx.x;
    int t = threadIdx.x;
    int w = t >> 5, l = t & 31;
    __shared__ __align__(16) float hv[Hh];
    __shared__ float logits[Gn];
    __shared__ float red[8];
    if (t < Hh) hv[t] = g_hn[b * Hh + t];
    __syncthreads();
    float4 h4 = *(const float4*)&hv[4 * l];

    float* oShape = out;
    float* oScale = out + (size_t)Bsz * Gn;
    float* oDrop  = out + 2 * (size_t)Bsz * Gn;

    for (int g = w; g < Gn; g += 8) {
        const float4 w1 = *(const float4*)(Wscale + (size_t)g * Hh + 4 * l);
        const float4 w2 = *(const float4*)(Wshape + (size_t)g * Hh + 4 * l);
        const float4 w3 = *(const float4*)(Wdrop  + (size_t)g * Hh + 4 * l);
        float p1 = w1.x * h4.x + w1.y * h4.y + w1.z * h4.z + w1.w * h4.w;
        float p2 = w2.x * h4.x + w2.y * h4.y + w2.z * h4.z + w2.w * h4.w;
        float p3 = w3.x * h4.x + w3.y * h4.y + w3.z * h4.z + w3.w * h4.w;
        #pragma unroll
        for (int o = 16; o > 0; o >>= 1) {
            p1 += __shfl_xor_sync(0xffffffffu, p1, o);
            p2 += __shfl_xor_sync(0xffffffffu, p2, o);
            p3 += __shfl_xor_sync(0xffffffffu, p3, o);
        }
        if (l == 0) {
            oShape[(size_t)b * Gn + g] = p2 + bshape[g];
            oDrop [(size_t)b * Gn + g] = p3 + bdrop[g];
            logits[g] = p1 + bscale[g];
        }
    }
    __syncthreads();

    // softmax over logits[0..1023]; thread owns 4 strided elements
    float l4[4];
    float mx = -3.0e38f;
    #pragma unroll
    for (int q = 0; q < 4; q++) {
        l4[q] = logits[t + 256 * q];
        mx = fmaxf(mx, l4[q]);
    }
    #pragma unroll
    for (int o = 16; o > 0; o >>= 1)
        mx = fmaxf(mx, __shfl_xor_sync(0xffffffffu, mx, o));
    if (l == 0) red[w] = mx;
    __syncthreads();
    if (t < 8) {
        float x = red[t];
        #pragma unroll
        for (int o = 4; o > 0; o >>= 1)
            x = fmaxf(x, __shfl_xor_sync(0x000000ffu, x, o));
        if (t == 0) red[0] = x;
    }
    __syncthreads();
    mx = red[0];
    __syncthreads();

    float sum = 0.f;
    float e4[4];
    #pragma unroll
    for (int q = 0; q < 4; q++) {
        e4[q] = expf(l4[q] - mx);
        sum += e4[q];
    }
    #pragma unroll
    for (int o = 16; o > 0; o >>= 1)
        sum += __shfl_xor_sync(0xffffffffu, sum, o);
    if (l == 0) red[w] = sum;
    __syncthreads();
    if (t < 8) {
        float x = red[t];
        #pragma unroll
        for (int o = 4; o > 0; o >>= 1)
            x += __shfl_xor_sync(0x000000ffu, x, o);
        if (t == 0) red[0] = x;
    }
    __syncthreads();
    float S = red[0];
    float invS = 1.f / S;
    #pragma unroll
    for (int q = 0; q < 4; q++)
        oScale[(size_t)b * Gn + t + 256 * q] = e4[q] * invS;
}

// ---------------- launch ----------------
extern "C" void kernel_launch(void* const* d_in, const int* in_sizes, int n_in,
                              void* d_out, int out_size) {
    const float* z      = (const float*)d_in[0];
    const float* Wc     = (const float*)d_in[1];
    const float* bc     = (const float*)d_in[2];
    const float* W1     = (const float*)d_in[3];
    const float* b1     = (const float*)d_in[4];
    const float* gamma  = (const float*)d_in[5];
    const float* beta   = (const float*)d_in[6];
    const float* Wscale = (const float*)d_in[7];
    const float* bscale = (const float*)d_in[8];
    const float* Wshape = (const float*)d_in[9];
    const float* bshape = (const float*)d_in[10];
    const float* Wdrop  = (const float*)d_in[11];
    const float* bdrop  = (const float*)d_in[12];
    float* out = (float*)d_out;

    k_pairs<<<Gn, 128>>>();
    k_cexp<<<Bsz, 256>>>(z, Wc, bc);
    k_gemm<<<dim3(NCHUNK, 2), 256>>>(W1, out + 3 * (size_t)Bsz * Gn);
    k_bn<<<1, 128>>>(b1, gamma, beta);
    k_heads<<<Bsz, 256>>>(Wscale, bscale, Wshape, bshape, Wdrop, bdrop, out);
}

// round 6
// speedup vs baseline: 1.1631x; 1.1631x over previous
#include <cuda_runtime.h>
#include <cuda_bf16.h>
#include <math.h>
#include <stdint.h>

#define Gn   1024
#define NIN  64
#define Hh   128
#define Bsz  256
#define Pn   523776
#define KT   64          // k per tile
#define NT   8184        // Pn / KT
#define KSPLIT 74

// ---------------- device scratch ----------------
__device__ float        g_Em[Bsz * Gn];   // exp(-c)  [b][g]
__device__ float        g_Ep[Bsz * Gn];   // exp(+c)  [b][g]
__device__ unsigned int g_pairs[Pn];      // (i<<16)|j
__device__ float        g_h [Bsz * Hh];   // split-K accumulator
__device__ float        g_hn[Bsz * Hh];   // post-BN ReLU hidden

// ---------------- helpers ----------------
__device__ __forceinline__ uint32_t smem_u32(const void* p) {
    uint32_t a;
    asm("{ .reg .u64 t; cvta.to.shared.u64 t, %1; cvt.u32.u64 %0, t; }" : "=r"(a) : "l"(p));
    return a;
}
__device__ __forceinline__ void ldsm_x4(uint32_t* r, uint32_t addr) {
    asm volatile("ldmatrix.sync.aligned.m8n8.x4.shared.b16 {%0,%1,%2,%3}, [%4];"
                 : "=r"(r[0]), "=r"(r[1]), "=r"(r[2]), "=r"(r[3]) : "r"(addr));
}
__device__ __forceinline__ void ldsm_x2(uint32_t* r, uint32_t addr) {
    asm volatile("ldmatrix.sync.aligned.m8n8.x2.shared.b16 {%0,%1}, [%2];"
                 : "=r"(r[0]), "=r"(r[1]) : "r"(addr));
}
__device__ __forceinline__ void mma16816(float* c, const uint32_t* a, const uint32_t* b) {
    asm volatile(
        "mma.sync.aligned.m16n8k16.row.col.f32.bf16.bf16.f32 "
        "{%0,%1,%2,%3}, {%4,%5,%6,%7}, {%8,%9}, {%0,%1,%2,%3};"
        : "+f"(c[0]), "+f"(c[1]), "+f"(c[2]), "+f"(c[3])
        : "r"(a[0]), "r"(a[1]), "r"(a[2]), "r"(a[3]), "r"(b[0]), "r"(b[1]));
}
// pack hi bf16x2 and residual-lo bf16x2 from two fp32 (lo half = s0)
__device__ __forceinline__ void split2(float s0, float s1, uint32_t& hp, uint32_t& lp) {
    asm("cvt.rn.bf16x2.f32 %0, %1, %2;" : "=r"(hp) : "f"(s1), "f"(s0));
    float f0h = __uint_as_float(hp << 16);
    float f1h = __uint_as_float(hp & 0xffff0000u);
    float r0 = s0 - f0h, r1 = s1 - f1h;
    asm("cvt.rn.bf16x2.f32 %0, %1, %2;" : "=r"(lp) : "f"(r1), "f"(r0));
}

// ---------------- kernel 0: pair table ----------------
__global__ void k_pairs() {
    int i = blockIdx.x;
    if (i >= Gn - 1) return;
    int off = i * (Gn - 1) - (i * (i - 1)) / 2;
    for (int j = i + 1 + threadIdx.x; j < Gn; j += blockDim.x)
        g_pairs[off + (j - i - 1)] = ((unsigned)i << 16) | (unsigned)j;
}

// ---------------- kernel 1: c = z@Wc.T + bc ; exp tables ; zero g_h ------
__global__ void k_cexp(const float* __restrict__ z,
                       const float* __restrict__ Wc,
                       const float* __restrict__ bc) {
    int b = blockIdx.x;
    int t = threadIdx.x;
    int w = t >> 5, l = t & 31;
    __shared__ float zv[NIN];
    if (t < NIN) zv[t] = z[b * NIN + t];
    if (t < Hh)  g_h[b * Hh + t] = 0.f;
    __syncthreads();
    float z0 = zv[2 * l], z1 = zv[2 * l + 1];
    for (int g = w; g < Gn; g += 8) {
        float2 wv = *(const float2*)(Wc + (size_t)g * NIN + 2 * l);
        float p = wv.x * z0 + wv.y * z1;
        #pragma unroll
        for (int o = 16; o > 0; o >>= 1)
            p += __shfl_xor_sync(0xffffffffu, p, o);
        if (l == 0) {
            float c = p + bc[g];
            g_Em[b * Gn + g] = expf(-c);
            g_Ep[b * Gn + g] = expf(c);
        }
    }
}

// ---------------- kernel 2: fused sigma gen + bf16-split HMMA GEMM -------
// grid (KSPLIT, 2), 256 threads. CTA tile: M=128 batch x N=128 hidden, split-K.
// smem tiles [128 rows][64 bf16] with 144-byte pitch (conflict-free):
//   A_hi +0, A_lo +18432, B_hi +36864, B_lo +55296
#define PITCH 144
#define TILE_B (128 * PITCH)
#define SMEM_TOTAL (4 * TILE_B)

__global__ void __launch_bounds__(256, 1)
k_mma(const float* __restrict__ W1, float* __restrict__ outSigma) {
    extern __shared__ char smem[];
    const uint32_t sb = smem_u32(smem);
    const uint32_t Ah = sb, Al = sb + TILE_B, Bh = sb + 2 * TILE_B, Bl = sb + 3 * TILE_B;

    const int t = threadIdx.x, wid = t >> 5, lane = t & 31;
    const int kz = blockIdx.x;
    const int btile = blockIdx.y * 128;
    const int warp_m = wid & 1;        // 2 warps over M (64 rows each)
    const int warp_n = wid >> 1;       // 4 warps over N (32 cols each)

    const int t0 = (kz * NT) / KSPLIT;
    const int t1 = ((kz + 1) * NT) / KSPLIT;

    float acc[4][4][4];
    #pragma unroll
    for (int mi = 0; mi < 4; mi++)
        #pragma unroll
        for (int ni = 0; ni < 4; ni++)
            #pragma unroll
            for (int q = 0; q < 4; q++) acc[mi][ni][q] = 0.f;

    const int row0 = wid * 16;   // producer: 16 rows per warp (A rows & B rows)

    // precomputed ldmatrix lane addresses (byte offsets into tiles)
    const uint32_t a_row = (uint32_t)(warp_m * 64 + (lane & 15));
    const uint32_t a_koff = (uint32_t)((lane >> 4) * 16);
    const uint32_t b_row = (uint32_t)(warp_n * 32 + (lane & 7));
    const uint32_t b_koff = (uint32_t)(((lane >> 3) & 1) * 16);

    for (int tt = t0; tt < t1; tt++) {
        const int pk = tt * KT;
        __syncthreads();   // previous step's mma reads done before overwrite

        // ---- pair indices for this thread's two k columns
        uint2 pr = *(const uint2*)(g_pairs + pk + 2 * lane);
        const int i0 = (int)(pr.x >> 16), j0 = (int)(pr.x & 0xffffu);
        const int i1 = (int)(pr.y >> 16), j1 = (int)(pr.y & 0xffffu);

        // ---- generate sigma: 16 rows; fp32 out (coalesced) + bf16 hi/lo smem
        #pragma unroll 4
        for (int r = 0; r < 16; r++) {
            const int m = row0 + r;
            const int brow = btile + m;
            const float* emr = g_Em + (size_t)brow * Gn;
            const float* epr = g_Ep + (size_t)brow * Gn;
            float s0 = __ldg(emr + i0) * __ldg(epr + j0);
            float s1 = __ldg(emr + i1) * __ldg(epr + j1);
            *(float2*)(outSigma + (size_t)brow * Pn + pk + 2 * lane) = make_float2(s0, s1);
            uint32_t hp, lp;
            split2(s0, s1, hp, lp);
            uint32_t off = (uint32_t)m * PITCH + lane * 4;
            asm volatile("st.shared.b32 [%0], %1;" :: "r"(Ah + off), "r"(hp) : "memory");
            asm volatile("st.shared.b32 [%0], %1;" :: "r"(Al + off), "r"(lp) : "memory");
        }
        // ---- W1 tile: 16 rows -> bf16 hi/lo smem
        #pragma unroll 4
        for (int r = 0; r < 16; r++) {
            const int n = row0 + r;
            float2 wv = *(const float2*)(W1 + (size_t)n * Pn + pk + 2 * lane);
            uint32_t hp, lp;
            split2(wv.x, wv.y, hp, lp);
            uint32_t off = (uint32_t)n * PITCH + lane * 4;
            asm volatile("st.shared.b32 [%0], %1;" :: "r"(Bh + off), "r"(hp) : "memory");
            asm volatile("st.shared.b32 [%0], %1;" :: "r"(Bl + off), "r"(lp) : "memory");
        }
        __syncthreads();

        // ---- consume: 4 k16 sub-steps
        #pragma unroll
        for (int kk = 0; kk < 4; kk++) {
            uint32_t bhf[4][2], blf[4][2];
            #pragma unroll
            for (int ni = 0; ni < 4; ni++) {
                uint32_t boff = (b_row + ni * 8) * PITCH + kk * 32 + b_koff;
                ldsm_x2(bhf[ni], Bh + boff);
                ldsm_x2(blf[ni], Bl + boff);
            }
            #pragma unroll
            for (int mi = 0; mi < 4; mi++) {
                uint32_t aoff = (a_row + mi * 16) * PITCH + kk * 32 + a_koff;
                uint32_t ahf[4], alf[4];
                ldsm_x4(ahf, Ah + aoff);
                ldsm_x4(alf, Al + aoff);
                #pragma unroll
                for (int ni = 0; ni < 4; ni++) {
                    mma16816(acc[mi][ni], ahf, bhf[ni]);
                    mma16816(acc[mi][ni], ahf, blf[ni]);
                    mma16816(acc[mi][ni], alf, bhf[ni]);
                }
            }
        }
    }

    // ---- epilogue: fragment -> split-K atomic reduction into g_h
    const int rbase = btile + warp_m * 64 + (lane >> 2);
    const int cbase = warp_n * 32 + (lane & 3) * 2;
    #pragma unroll
    for (int mi = 0; mi < 4; mi++) {
        #pragma unroll
        for (int ni = 0; ni < 4; ni++) {
            int r0i = rbase + mi * 16;
            int c0i = cbase + ni * 8;
            atomicAdd(&g_h[(r0i    ) * Hh + c0i    ], acc[mi][ni][0]);
            atomicAdd(&g_h[(r0i    ) * Hh + c0i + 1], acc[mi][ni][1]);
            atomicAdd(&g_h[(r0i + 8) * Hh + c0i    ], acc[mi][ni][2]);
            atomicAdd(&g_h[(r0i + 8) * Hh + c0i + 1], acc[mi][ni][3]);
        }
    }
}

// ---------------- kernel 3: BatchNorm + ReLU (1024 threads) --------------
__global__ void k_bn(const float* __restrict__ b1,
                     const float* __restrict__ gamma,
                     const float* __restrict__ beta) {
    int t = threadIdx.x;
    int hh = t & 127, seg = t >> 7;          // 8 segments of 32 batch rows
    __shared__ float ssum[8][128], ssq[8][128], smean[128], sinv[128];
    float bb = b1[hh];
    float s = 0.f, q = 0.f;
    #pragma unroll 8
    for (int b = seg * 32; b < seg * 32 + 32; b++) {
        float v = g_h[b * Hh + hh] + bb;
        s += v; q += v * v;
    }
    ssum[seg][hh] = s; ssq[seg][hh] = q;
    __syncthreads();
    if (t < 128) {
        float S = 0.f, Q = 0.f;
        #pragma unroll
        for (int g = 0; g < 8; g++) { S += ssum[g][t]; Q += ssq[g][t]; }
        float mean = S * (1.f / Bsz);
        float var  = Q * (1.f / Bsz) - mean * mean;
        smean[t] = mean;
        sinv[t]  = rsqrtf(var + 1e-3f);
    }
    __syncthreads();
    float mean = smean[hh], inv = sinv[hh];
    float ga = gamma[hh], be = beta[hh];
    #pragma unroll 8
    for (int b = seg * 32; b < seg * 32 + 32; b++) {
        float v = g_h[b * Hh + hh] + bb;
        float y = ga * (v - mean) * inv + be;
        g_hn[b * Hh + hh] = fmaxf(y, 0.f);
    }
}

// ---------------- kernel 4: heads + softmax ------------------------------
__global__ void k_heads(const float* __restrict__ Wscale, const float* __restrict__ bscale,
                        const float* __restrict__ Wshape, const float* __restrict__ bshape,
                        const float* __restrict__ Wdrop,  const float* __restrict__ bdrop,
                        float* __restrict__ out) {
    int b = blockIdx.x;
    int t = threadIdx.x;
    int w = t >> 5, l = t & 31;
    __shared__ __align__(16) float hv[Hh];
    __shared__ float logits[Gn];
    __shared__ float red[8];
    if (t < Hh) hv[t] = g_hn[b * Hh + t];
    __syncthreads();
    float4 h4 = *(const float4*)&hv[4 * l];

    float* oShape = out;
    float* oScale = out + (size_t)Bsz * Gn;
    float* oDrop  = out + 2 * (size_t)Bsz * Gn;

    for (int g = w; g < Gn; g += 8) {
        const float4 w1 = *(const float4*)(Wscale + (size_t)g * Hh + 4 * l);
        const float4 w2 = *(const float4*)(Wshape + (size_t)g * Hh + 4 * l);
        const float4 w3 = *(const float4*)(Wdrop  + (size_t)g * Hh + 4 * l);
        float p1 = w1.x * h4.x + w1.y * h4.y + w1.z * h4.z + w1.w * h4.w;
        float p2 = w2.x * h4.x + w2.y * h4.y + w2.z * h4.z + w2.w * h4.w;
        float p3 = w3.x * h4.x + w3.y * h4.y + w3.z * h4.z + w3.w * h4.w;
        #pragma unroll
        for (int o = 16; o > 0; o >>= 1) {
            p1 += __shfl_xor_sync(0xffffffffu, p1, o);
            p2 += __shfl_xor_sync(0xffffffffu, p2, o);
            p3 += __shfl_xor_sync(0xffffffffu, p3, o);
        }
        if (l == 0) {
            oShape[(size_t)b * Gn + g] = p2 + bshape[g];
            oDrop [(size_t)b * Gn + g] = p3 + bdrop[g];
            logits[g] = p1 + bscale[g];
        }
    }
    __syncthreads();

    float l4[4];
    float mx = -3.0e38f;
    #pragma unroll
    for (int q = 0; q < 4; q++) {
        l4[q] = logits[t + 256 * q];
        mx = fmaxf(mx, l4[q]);
    }
    #pragma unroll
    for (int o = 16; o > 0; o >>= 1)
        mx = fmaxf(mx, __shfl_xor_sync(0xffffffffu, mx, o));
    if (l == 0) red[w] = mx;
    __syncthreads();
    if (t < 8) {
        float x = red[t];
        #pragma unroll
        for (int o = 4; o > 0; o >>= 1)
            x = fmaxf(x, __shfl_xor_sync(0x000000ffu, x, o));
        if (t == 0) red[0] = x;
    }
    __syncthreads();
    mx = red[0];
    __syncthreads();

    float sum = 0.f;
    float e4[4];
    #pragma unroll
    for (int q = 0; q < 4; q++) {
        e4[q] = expf(l4[q] - mx);
        sum += e4[q];
    }
    #pragma unroll
    for (int o = 16; o > 0; o >>= 1)
        sum += __shfl_xor_sync(0xffffffffu, sum, o);
    if (l == 0) red[w] = sum;
    __syncthreads();
    if (t < 8) {
        float x = red[t];
        #pragma unroll
        for (int o = 4; o > 0; o >>= 1)
            x += __shfl_xor_sync(0x000000ffu, x, o);
        if (t == 0) red[0] = x;
    }
    __syncthreads();
    float S = red[0];
    float invS = 1.f / S;
    #pragma unroll
    for (int q = 0; q < 4; q++)
        oScale[(size_t)b * Gn + t + 256 * q] = e4[q] * invS;
}

// ---------------- launch ----------------
extern "C" void kernel_launch(void* const* d_in, const int* in_sizes, int n_in,
                              void* d_out, int out_size) {
    const float* z      = (const float*)d_in[0];
    const float* Wc     = (const float*)d_in[1];
    const float* bc     = (const float*)d_in[2];
    const float* W1     = (const float*)d_in[3];
    const float* b1     = (const float*)d_in[4];
    const float* gamma  = (const float*)d_in[5];
    const float* beta   = (const float*)d_in[6];
    const float* Wscale = (const float*)d_in[7];
    const float* bscale = (const float*)d_in[8];
    const float* Wshape = (const float*)d_in[9];
    const float* bshape = (const float*)d_in[10];
    const float* Wdrop  = (const float*)d_in[11];
    const float* bdrop  = (const float*)d_in[12];
    float* out = (float*)d_out;

    static int smem_set = 0;
    if (!smem_set) {
        cudaFuncSetAttribute(k_mma, cudaFuncAttributeMaxDynamicSharedMemorySize, SMEM_TOTAL);
        smem_set = 1;
    }

    k_pairs<<<Gn, 128>>>();
    k_cexp<<<Bsz, 256>>>(z, Wc, bc);
    k_mma<<<dim3(KSPLIT, 2), 256, SMEM_TOTAL>>>(W1, out + 3 * (size_t)Bsz * Gn);
    k_bn<<<1, 1024>>>(b1, gamma, beta);
    k_heads<<<Bsz, 256>>>(Wscale, bscale, Wshape, bshape, Wdrop, bdrop, out);
}

// round 7
// speedup vs baseline: 1.1691x; 1.0051x over previous
#include <cuda_runtime.h>
#include <cuda_bf16.h>
#include <math.h>
#include <stdint.h>

#define Gn   1024
#define NIN  64
#define Hh   128
#define Bsz  256
#define Pn   523776
#define KT   64          // k per tile
#define NT   8184        // Pn / KT
#define KSPLIT 74

// ---------------- device scratch ----------------
__device__ float        g_Em[Bsz * Gn];   // exp(-c)  [b][g]
__device__ float        g_Ep[Bsz * Gn];   // exp(+c)  [b][g]
__device__ unsigned int g_pairs[Pn];      // (i<<16)|j
__device__ float        g_h [Bsz * Hh];   // split-K accumulator
__device__ float        g_hn[Bsz * Hh];   // post-BN ReLU hidden

// ---------------- helpers ----------------
__device__ __forceinline__ uint32_t smem_u32(const void* p) {
    uint32_t a;
    asm("{ .reg .u64 t; cvta.to.shared.u64 t, %1; cvt.u32.u64 %0, t; }" : "=r"(a) : "l"(p));
    return a;
}
__device__ __forceinline__ void ldsm_x4(uint32_t* r, uint32_t addr) {
    asm volatile("ldmatrix.sync.aligned.m8n8.x4.shared.b16 {%0,%1,%2,%3}, [%4];"
                 : "=r"(r[0]), "=r"(r[1]), "=r"(r[2]), "=r"(r[3]) : "r"(addr));
}
__device__ __forceinline__ void mma16816(float* c, const uint32_t* a, const uint32_t* b) {
    asm volatile(
        "mma.sync.aligned.m16n8k16.row.col.f32.bf16.bf16.f32 "
        "{%0,%1,%2,%3}, {%4,%5,%6,%7}, {%8,%9}, {%0,%1,%2,%3};"
        : "+f"(c[0]), "+f"(c[1]), "+f"(c[2]), "+f"(c[3])
        : "r"(a[0]), "r"(a[1]), "r"(a[2]), "r"(a[3]), "r"(b[0]), "r"(b[1]));
}
// pack hi bf16x2 and residual-lo bf16x2 from two fp32 (lo half = s0)
__device__ __forceinline__ void split2(float s0, float s1, uint32_t& hp, uint32_t& lp) {
    asm("cvt.rn.bf16x2.f32 %0, %1, %2;" : "=r"(hp) : "f"(s1), "f"(s0));
    float f0h = __uint_as_float(hp << 16);
    float f1h = __uint_as_float(hp & 0xffff0000u);
    float r0 = s0 - f0h, r1 = s1 - f1h;
    asm("cvt.rn.bf16x2.f32 %0, %1, %2;" : "=r"(lp) : "f"(r1), "f"(r0));
}

// ---------------- kernel 0: pair table ----------------
__global__ void k_pairs() {
    int i = blockIdx.x;
    if (i >= Gn - 1) return;
    int off = i * (Gn - 1) - (i * (i - 1)) / 2;
    for (int j = i + 1 + threadIdx.x; j < Gn; j += blockDim.x)
        g_pairs[off + (j - i - 1)] = ((unsigned)i << 16) | (unsigned)j;
}

// ---------------- kernel 1: c = z@Wc.T + bc ; exp tables ; zero g_h ------
__global__ void k_cexp(const float* __restrict__ z,
                       const float* __restrict__ Wc,
                       const float* __restrict__ bc) {
    int b = blockIdx.x;
    int t = threadIdx.x;
    int w = t >> 5, l = t & 31;
    __shared__ float zv[NIN];
    if (t < NIN) zv[t] = z[b * NIN + t];
    if (t < Hh)  g_h[b * Hh + t] = 0.f;
    __syncthreads();
    float z0 = zv[2 * l], z1 = zv[2 * l + 1];
    for (int g = w; g < Gn; g += 8) {
        float2 wv = *(const float2*)(Wc + (size_t)g * NIN + 2 * l);
        float p = wv.x * z0 + wv.y * z1;
        #pragma unroll
        for (int o = 16; o > 0; o >>= 1)
            p += __shfl_xor_sync(0xffffffffu, p, o);
        if (l == 0) {
            float c = p + bc[g];
            g_Em[b * Gn + g] = expf(-c);
            g_Ep[b * Gn + g] = expf(c);
        }
    }
}

// ---------------- kernel 2: pipelined fused sigma gen + HMMA GEMM --------
// grid (KSPLIT, 2), 256 threads. CTA tile: M=128 batch x N=128 hidden, split-K.
// Double-buffered smem; register-prefetch of next tile's globals under the mma.
#define PITCH 144
#define TSZ   (128 * PITCH)      // 18432 per matrix
#define STG   (4 * TSZ)          // Ah, Al, Bh, Bl per stage = 73728
#define SMEM_TOTAL (2 * STG)

__global__ void __launch_bounds__(256, 1)
k_mma(const float* __restrict__ W1, float* __restrict__ outSigma) {
    extern __shared__ char smem[];
    const uint32_t sb = smem_u32(smem);

    const int t = threadIdx.x, wid = t >> 5, lane = t & 31;
    const int kz = blockIdx.x;
    const int btile = blockIdx.y * 128;
    const int warp_m = wid & 1;        // 2 warps over M (64 rows each)
    const int warp_n = wid >> 1;       // 4 warps over N (32 cols each)

    const int t0 = (kz * NT) / KSPLIT;
    const int t1 = ((kz + 1) * NT) / KSPLIT;

    float acc[4][4][4];
    #pragma unroll
    for (int mi = 0; mi < 4; mi++)
        #pragma unroll
        for (int ni = 0; ni < 4; ni++)
            #pragma unroll
            for (int q = 0; q < 4; q++) acc[mi][ni][q] = 0.f;

    const int row0 = wid * 16;   // producer: 16 rows per warp (A rows & B rows)

    // ldmatrix lane addressing
    const uint32_t a_row  = (uint32_t)(warp_m * 64 + (lane & 15));
    const uint32_t a_koff = (uint32_t)((lane >> 4) * 16);
    // B x4: pairs of n-blocks; lanes 16-31 take the +8-row block
    const uint32_t b_row4 = (uint32_t)(warp_n * 32 + (lane & 7) + ((lane >> 4) << 3));
    const uint32_t b_koff = (uint32_t)(((lane >> 3) & 1) * 16);

    // ---------------- prologue: produce tile t0 into stage 0 -------------
    {
        const int pk = t0 * KT;
        const uint32_t Ah = sb, Al = sb + TSZ, Bh = sb + 2 * TSZ, Bl = sb + 3 * TSZ;
        uint2 pr = *(const uint2*)(g_pairs + pk + 2 * lane);
        const int i0 = (int)(pr.x >> 16), j0 = (int)(pr.x & 0xffffu);
        const int i1 = (int)(pr.y >> 16), j1 = (int)(pr.y & 0xffffu);
        #pragma unroll 4
        for (int r = 0; r < 16; r++) {
            const int m = row0 + r;
            const int brow = btile + m;
            float s0 = __ldg(g_Em + (size_t)brow * Gn + i0) * __ldg(g_Ep + (size_t)brow * Gn + j0);
            float s1 = __ldg(g_Em + (size_t)brow * Gn + i1) * __ldg(g_Ep + (size_t)brow * Gn + j1);
            *(float2*)(outSigma + (size_t)brow * Pn + pk + 2 * lane) = make_float2(s0, s1);
            uint32_t hp, lp;
            split2(s0, s1, hp, lp);
            uint32_t off = (uint32_t)m * PITCH + lane * 4;
            asm volatile("st.shared.b32 [%0], %1;" :: "r"(Ah + off), "r"(hp) : "memory");
            asm volatile("st.shared.b32 [%0], %1;" :: "r"(Al + off), "r"(lp) : "memory");
        }
        #pragma unroll 4
        for (int r = 0; r < 16; r++) {
            const int n = row0 + r;
            float2 wv = *(const float2*)(W1 + (size_t)n * Pn + pk + 2 * lane);
            uint32_t hp, lp;
            split2(wv.x, wv.y, hp, lp);
            uint32_t off = (uint32_t)n * PITCH + lane * 4;
            asm volatile("st.shared.b32 [%0], %1;" :: "r"(Bh + off), "r"(hp) : "memory");
            asm volatile("st.shared.b32 [%0], %1;" :: "r"(Bl + off), "r"(lp) : "memory");
        }
    }
    // pair prefetch for tile t0+1 (addresses static -> no stall)
    uint2 pcur = make_uint2(0u, 0u);
    if (t0 + 1 < t1) pcur = *(const uint2*)(g_pairs + (t0 + 1) * KT + 2 * lane);
    __syncthreads();

    // prefetch registers
    float em0[16], ep0[16], em1[16], ep1[16];
    float2 pw[16];

    for (int tt = t0; tt < t1; tt++) {
        const int s = (tt - t0) & 1;
        const uint32_t Ah = sb + s * STG;
        const uint32_t Al = Ah + TSZ, Bh = Ah + 2 * TSZ, Bl = Ah + 3 * TSZ;
        const bool pf = (tt + 1 < t1);
        uint2 pnext = make_uint2(0u, 0u);

        // ---- (1) issue next tile's global loads into registers ----
        if (pf) {
            const int pkn = (tt + 1) * KT;
            const int i0 = (int)(pcur.x >> 16), j0 = (int)(pcur.x & 0xffffu);
            const int i1 = (int)(pcur.y >> 16), j1 = (int)(pcur.y & 0xffffu);
            #pragma unroll
            for (int r = 0; r < 16; r++) {
                const size_t brow = (size_t)(btile + row0 + r) * Gn;
                em0[r] = __ldg(g_Em + brow + i0);
                ep0[r] = __ldg(g_Ep + brow + j0);
                em1[r] = __ldg(g_Em + brow + i1);
                ep1[r] = __ldg(g_Ep + brow + j1);
            }
            #pragma unroll
            for (int r = 0; r < 16; r++)
                pw[r] = *(const float2*)(W1 + (size_t)(row0 + r) * Pn + pkn + 2 * lane);
            if (tt + 2 < t1)
                pnext = *(const uint2*)(g_pairs + (tt + 2) * KT + 2 * lane);
        }

        // ---- (2) mma over stage s (hides the loads above) ----
        #pragma unroll
        for (int kk = 0; kk < 4; kk++) {
            uint32_t bhf[4][2], blf[4][2];
            #pragma unroll
            for (int np = 0; np < 2; np++) {   // n-block pairs (0,1) and (2,3)
                uint32_t boff = (b_row4 + np * 16) * PITCH + kk * 32 + b_koff;
                uint32_t r4[4];
                ldsm_x4(r4, Bh + boff);
                bhf[2 * np][0] = r4[0]; bhf[2 * np][1] = r4[1];
                bhf[2 * np + 1][0] = r4[2]; bhf[2 * np + 1][1] = r4[3];
                ldsm_x4(r4, Bl + boff);
                blf[2 * np][0] = r4[0]; blf[2 * np][1] = r4[1];
                blf[2 * np + 1][0] = r4[2]; blf[2 * np + 1][1] = r4[3];
            }
            #pragma unroll
            for (int mi = 0; mi < 4; mi++) {
                uint32_t aoff = (a_row + mi * 16) * PITCH + kk * 32 + a_koff;
                uint32_t ahf[4], alf[4];
                ldsm_x4(ahf, Ah + aoff);
                ldsm_x4(alf, Al + aoff);
                #pragma unroll
                for (int ni = 0; ni < 4; ni++) {
                    mma16816(acc[mi][ni], ahf, bhf[ni]);
                    mma16816(acc[mi][ni], ahf, blf[ni]);
                    mma16816(acc[mi][ni], alf, bhf[ni]);
                }
            }
        }

        // ---- (3) convert prefetched data into stage s^1 + sigma STG ----
        if (pf) {
            const int pkn = (tt + 1) * KT;
            const uint32_t oA = sb + (s ^ 1) * STG;
            const uint32_t oAl = oA + TSZ, oBh = oA + 2 * TSZ, oBl = oA + 3 * TSZ;
            #pragma unroll 4
            for (int r = 0; r < 16; r++) {
                const int m = row0 + r;
                const int brow = btile + m;
                float s0 = em0[r] * ep0[r];
                float s1 = em1[r] * ep1[r];
                *(float2*)(outSigma + (size_t)brow * Pn + pkn + 2 * lane) = make_float2(s0, s1);
                uint32_t hp, lp;
                split2(s0, s1, hp, lp);
                uint32_t off = (uint32_t)m * PITCH + lane * 4;
                asm volatile("st.shared.b32 [%0], %1;" :: "r"(oA + off), "r"(hp) : "memory");
                asm volatile("st.shared.b32 [%0], %1;" :: "r"(oAl + off), "r"(lp) : "memory");
            }
            #pragma unroll 4
            for (int r = 0; r < 16; r++) {
                const int n = row0 + r;
                uint32_t hp, lp;
                split2(pw[r].x, pw[r].y, hp, lp);
                uint32_t off = (uint32_t)n * PITCH + lane * 4;
                asm volatile("st.shared.b32 [%0], %1;" :: "r"(oBh + off), "r"(hp) : "memory");
                asm volatile("st.shared.b32 [%0], %1;" :: "r"(oBl + off), "r"(lp) : "memory");
            }
            pcur = pnext;
        }
        __syncthreads();
    }

    // ---- epilogue: fragment -> split-K atomic reduction into g_h
    const int rbase = btile + warp_m * 64 + (lane >> 2);
    const int cbase = warp_n * 32 + (lane & 3) * 2;
    #pragma unroll
    for (int mi = 0; mi < 4; mi++) {
        #pragma unroll
        for (int ni = 0; ni < 4; ni++) {
            int r0i = rbase + mi * 16;
            int c0i = cbase + ni * 8;
            atomicAdd(&g_h[(r0i    ) * Hh + c0i    ], acc[mi][ni][0]);
            atomicAdd(&g_h[(r0i    ) * Hh + c0i + 1], acc[mi][ni][1]);
            atomicAdd(&g_h[(r0i + 8) * Hh + c0i    ], acc[mi][ni][2]);
            atomicAdd(&g_h[(r0i + 8) * Hh + c0i + 1], acc[mi][ni][3]);
        }
    }
}

// ---------------- kernel 3: BatchNorm + ReLU (1024 threads) --------------
__global__ void k_bn(const float* __restrict__ b1,
                     const float* __restrict__ gamma,
                     const float* __restrict__ beta) {
    int t = threadIdx.x;
    int hh = t & 127, seg = t >> 7;          // 8 segments of 32 batch rows
    __shared__ float ssum[8][128], ssq[8][128], smean[128], sinv[128];
    float bb = b1[hh];
    float s = 0.f, q = 0.f;
    #pragma unroll 8
    for (int b = seg * 32; b < seg * 32 + 32; b++) {
        float v = g_h[b * Hh + hh] + bb;
        s += v; q += v * v;
    }
    ssum[seg][hh] = s; ssq[seg][hh] = q;
    __syncthreads();
    if (t < 128) {
        float S = 0.f, Q = 0.f;
        #pragma unroll
        for (int g = 0; g < 8; g++) { S += ssum[g][t]; Q += ssq[g][t]; }
        float mean = S * (1.f / Bsz);
        float var  = Q * (1.f / Bsz) - mean * mean;
        smean[t] = mean;
        sinv[t]  = rsqrtf(var + 1e-3f);
    }
    __syncthreads();
    float mean = smean[hh], inv = sinv[hh];
    float ga = gamma[hh], be = beta[hh];
    #pragma unroll 8
    for (int b = seg * 32; b < seg * 32 + 32; b++) {
        float v = g_h[b * Hh + hh] + bb;
        float y = ga * (v - mean) * inv + be;
        g_hn[b * Hh + hh] = fmaxf(y, 0.f);
    }
}

// ---------------- kernel 4: heads + softmax ------------------------------
__global__ void k_heads(const float* __restrict__ Wscale, const float* __restrict__ bscale,
                        const float* __restrict__ Wshape, const float* __restrict__ bshape,
                        const float* __restrict__ Wdrop,  const float* __restrict__ bdrop,
                        float* __restrict__ out) {
    int b = blockIdx.x;
    int t = threadIdx.x;
    int w = t >> 5, l = t & 31;
    __shared__ __align__(16) float hv[Hh];
    __shared__ float logits[Gn];
    __shared__ float red[8];
    if (t < Hh) hv[t] = g_hn[b * Hh + t];
    __syncthreads();
    float4 h4 = *(const float4*)&hv[4 * l];

    float* oShape = out;
    float* oScale = out + (size_t)Bsz * Gn;
    float* oDrop  = out + 2 * (size_t)Bsz * Gn;

    for (int g = w; g < Gn; g += 8) {
        const float4 w1 = *(const float4*)(Wscale + (size_t)g * Hh + 4 * l);
        const float4 w2 = *(const float4*)(Wshape + (size_t)g * Hh + 4 * l);
        const float4 w3 = *(const float4*)(Wdrop  + (size_t)g * Hh + 4 * l);
        float p1 = w1.x * h4.x + w1.y * h4.y + w1.z * h4.z + w1.w * h4.w;
        float p2 = w2.x * h4.x + w2.y * h4.y + w2.z * h4.z + w2.w * h4.w;
        float p3 = w3.x * h4.x + w3.y * h4.y + w3.z * h4.z + w3.w * h4.w;
        #pragma unroll
        for (int o = 16; o > 0; o >>= 1) {
            p1 += __shfl_xor_sync(0xffffffffu, p1, o);
            p2 += __shfl_xor_sync(0xffffffffu, p2, o);
            p3 += __shfl_xor_sync(0xffffffffu, p3, o);
        }
        if (l == 0) {
            oShape[(size_t)b * Gn + g] = p2 + bshape[g];
            oDrop [(size_t)b * Gn + g] = p3 + bdrop[g];
            logits[g] = p1 + bscale[g];
        }
    }
    __syncthreads();

    float l4[4];
    float mx = -3.0e38f;
    #pragma unroll
    for (int q = 0; q < 4; q++) {
        l4[q] = logits[t + 256 * q];
        mx = fmaxf(mx, l4[q]);
    }
    #pragma unroll
    for (int o = 16; o > 0; o >>= 1)
        mx = fmaxf(mx, __shfl_xor_sync(0xffffffffu, mx, o));
    if (l == 0) red[w] = mx;
    __syncthreads();
    if (t < 8) {
        float x = red[t];
        #pragma unroll
        for (int o = 4; o > 0; o >>= 1)
            x = fmaxf(x, __shfl_xor_sync(0x000000ffu, x, o));
        if (t == 0) red[0] = x;
    }
    __syncthreads();
    mx = red[0];
    __syncthreads();

    float sum = 0.f;
    float e4[4];
    #pragma unroll
    for (int q = 0; q < 4; q++) {
        e4[q] = expf(l4[q] - mx);
        sum += e4[q];
    }
    #pragma unroll
    for (int o = 16; o > 0; o >>= 1)
        sum += __shfl_xor_sync(0xffffffffu, sum, o);
    if (l == 0) red[w] = sum;
    __syncthreads();
    if (t < 8) {
        float x = red[t];
        #pragma unroll
        for (int o = 4; o > 0; o >>= 1)
            x += __shfl_xor_sync(0x000000ffu, x, o);
        if (t == 0) red[0] = x;
    }
    __syncthreads();
    float S = red[0];
    float invS = 1.f / S;
    #pragma unroll
    for (int q = 0; q < 4; q++)
        oScale[(size_t)b * Gn + t + 256 * q] = e4[q] * invS;
}

// ---------------- launch ----------------
extern "C" void kernel_launch(void* const* d_in, const int* in_sizes, int n_in,
                              void* d_out, int out_size) {
    const float* z      = (const float*)d_in[0];
    const float* Wc     = (const float*)d_in[1];
    const float* bc     = (const float*)d_in[2];
    const float* W1     = (const float*)d_in[3];
    const float* b1     = (const float*)d_in[4];
    const float* gamma  = (const float*)d_in[5];
    const float* beta   = (const float*)d_in[6];
    const float* Wscale = (const float*)d_in[7];
    const float* bscale = (const float*)d_in[8];
    const float* Wshape = (const float*)d_in[9];
    const float* bshape = (const float*)d_in[10];
    const float* Wdrop  = (const float*)d_in[11];
    const float* bdrop  = (const float*)d_in[12];
    float* out = (float*)d_out;

    static int smem_set = 0;
    if (!smem_set) {
        cudaFuncSetAttribute(k_mma, cudaFuncAttributeMaxDynamicSharedMemorySize, SMEM_TOTAL);
        smem_set = 1;
    }

    k_pairs<<<Gn, 128>>>();
    k_cexp<<<Bsz, 256>>>(z, Wc, bc);
    k_mma<<<dim3(KSPLIT, 2), 256, SMEM_TOTAL>>>(W1, out + 3 * (size_t)Bsz * Gn);
    k_bn<<<1, 1024>>>(b1, gamma, beta);
    k_heads<<<Bsz, 256>>>(Wscale, bscale, Wshape, bshape, Wdrop, bdrop, out);
}